// round 1
// baseline (speedup 1.0000x reference)
#include <cuda_runtime.h>
#include <math.h>

// Problem dims (fixed by the reference setup_inputs)
#define N_CTX   4096
#define D_MODEL 2048

// Scratch (allocation-free rule: __device__ globals)
__device__ float g_Q[(size_t)N_CTX * D_MODEL];   // 32 MB
__device__ float g_S[(size_t)N_CTX * N_CTX];     // 64 MB (scores, softmaxed in place)
__device__ float g_A[(size_t)N_CTX * D_MODEL];   // 32 MB

// ---------------------------------------------------------------------------
// Tiled SIMT fp32 GEMM.
//   C[M,N] = A[M,K] @ op(B)
//   TRANS_B=1: B is [N,K] row-major (C = A @ B^T)
//   TRANS_B=0: B is [K,N] row-major (C = A @ B)
//   CAUSAL_SKIP=1: skip output blocks entirely above the diagonal (scores GEMM)
//   CAUSAL_K=1:   limit k-loop to k < m0+BM (P @ x GEMM; P rows are zero beyond i)
// Tile: 128x128x16, 256 threads, 8x8 accumulators per thread.
// All dims here are multiples of the tile sizes (4096/2048 M,N; K mult of 16),
// so no bounds checks.
// ---------------------------------------------------------------------------
template <int TRANS_B, int CAUSAL_SKIP, int CAUSAL_K>
__global__ __launch_bounds__(256)
void gemm_kernel(const float* __restrict__ A,
                 const float* __restrict__ B,
                 float* __restrict__ C,
                 int M, int N, int K)
{
    constexpr int BM = 128, BN = 128, BK = 16;
    const int m0 = blockIdx.y * BM;
    const int n0 = blockIdx.x * BN;

    if (CAUSAL_SKIP && n0 >= m0 + BM) return;   // block fully above diagonal

    const int kEnd = CAUSAL_K ? min(K, m0 + BM) : K;

    __shared__ float As[BK][BM];
    __shared__ float Bs[BK][BN];

    float acc[8][8];
    #pragma unroll
    for (int i = 0; i < 8; i++)
        #pragma unroll
        for (int j = 0; j < 8; j++)
            acc[i][j] = 0.0f;

    const int tid = threadIdx.x;
    const int tm  = (tid / 16) * 8;
    const int tn  = (tid % 16) * 8;

    for (int k0 = 0; k0 < kEnd; k0 += BK) {
        // ---- load A tile [BM x BK], store transposed As[k][m] ----
        #pragma unroll
        for (int i = 0; i < 2; i++) {
            int idx = tid + i * 256;            // 0..511 float4s
            int row = idx >> 2;                 // 0..127
            int c4  = (idx & 3) * 4;            // 0,4,8,12
            float4 v = *(const float4*)(A + (size_t)(m0 + row) * K + k0 + c4);
            As[c4 + 0][row] = v.x;
            As[c4 + 1][row] = v.y;
            As[c4 + 2][row] = v.z;
            As[c4 + 3][row] = v.w;
        }
        // ---- load B tile, store Bs[k][n] ----
        if (TRANS_B) {
            #pragma unroll
            for (int i = 0; i < 2; i++) {
                int idx = tid + i * 256;
                int row = idx >> 2;             // n within tile
                int c4  = (idx & 3) * 4;        // k within tile
                float4 v = *(const float4*)(B + (size_t)(n0 + row) * K + k0 + c4);
                Bs[c4 + 0][row] = v.x;
                Bs[c4 + 1][row] = v.y;
                Bs[c4 + 2][row] = v.z;
                Bs[c4 + 3][row] = v.w;
            }
        } else {
            #pragma unroll
            for (int i = 0; i < 2; i++) {
                int idx = tid + i * 256;
                int row = idx >> 5;             // k within tile (0..15)
                int c4  = (idx & 31) * 4;       // n within tile
                float4 v = *(const float4*)(B + (size_t)(k0 + row) * N + n0 + c4);
                *(float4*)&Bs[row][c4] = v;
            }
        }
        __syncthreads();

        // ---- compute ----
        #pragma unroll
        for (int kk = 0; kk < BK; kk++) {
            float ra[8], rb[8];
            #pragma unroll
            for (int i = 0; i < 8; i++) ra[i] = As[kk][tm + i];
            #pragma unroll
            for (int j = 0; j < 8; j++) rb[j] = Bs[kk][tn + j];
            #pragma unroll
            for (int i = 0; i < 8; i++)
                #pragma unroll
                for (int j = 0; j < 8; j++)
                    acc[i][j] = fmaf(ra[i], rb[j], acc[i][j]);
        }
        __syncthreads();
    }

    // ---- store ----
    #pragma unroll
    for (int i = 0; i < 8; i++) {
        #pragma unroll
        for (int j = 0; j < 8; j += 4) {
            float4 v = make_float4(acc[i][j], acc[i][j + 1], acc[i][j + 2], acc[i][j + 3]);
            *(float4*)(C + (size_t)(m0 + tm + i) * N + n0 + tn + j) = v;
        }
    }
}

// ---------------------------------------------------------------------------
// Causal row softmax, in place. One block per row.
// Row i: softmax over j <= i; writes 0 for j > i (matches -inf mask).
// Never reads S beyond the causal region (those blocks were skipped in GEMM2).
// ---------------------------------------------------------------------------
__global__ __launch_bounds__(256)
void softmax_kernel(float* __restrict__ S, int n)
{
    const int row   = blockIdx.x;
    float* srow     = S + (size_t)row * n;
    const int valid = row + 1;
    const int tid   = threadIdx.x;

    __shared__ float red[256];

    // max over valid entries
    float m = -INFINITY;
    for (int j = tid; j < valid; j += 256) m = fmaxf(m, srow[j]);
    red[tid] = m;
    __syncthreads();
    #pragma unroll
    for (int s = 128; s > 0; s >>= 1) {
        if (tid < s) red[tid] = fmaxf(red[tid], red[tid + s]);
        __syncthreads();
    }
    m = red[0];
    __syncthreads();

    // sum of exp
    float sum = 0.0f;
    for (int j = tid; j < valid; j += 256) sum += __expf(srow[j] - m);
    red[tid] = sum;
    __syncthreads();
    #pragma unroll
    for (int s = 128; s > 0; s >>= 1) {
        if (tid < s) red[tid] += red[tid + s];
        __syncthreads();
    }
    sum = red[0];
    const float inv = 1.0f / sum;

    // normalize + zero the masked tail
    for (int j = tid; j < n; j += 256) {
        float v = (j < valid) ? __expf(srow[j] - m) * inv : 0.0f;
        srow[j] = v;
    }
}

// ---------------------------------------------------------------------------
extern "C" void kernel_launch(void* const* d_in, const int* in_sizes, int n_in,
                              void* d_out, int out_size)
{
    const float* x   = (const float*)d_in[0];
    const float* Wqk = (const float*)d_in[1];
    const float* Wov = (const float*)d_in[2];
    float* out       = (float*)d_out;

    float *Q, *S, *A;
    cudaGetSymbolAddress((void**)&Q, g_Q);
    cudaGetSymbolAddress((void**)&S, g_S);
    cudaGetSymbolAddress((void**)&A, g_A);

    // 1) Q = x @ Wqk^T                       [4096, 2048]
    gemm_kernel<1, 0, 0><<<dim3(D_MODEL / 128, N_CTX / 128), 256>>>(
        x, Wqk, Q, N_CTX, D_MODEL, D_MODEL);

    // 2) S = Q @ x^T (lower-triangular blocks only)   [4096, 4096]
    gemm_kernel<1, 1, 0><<<dim3(N_CTX / 128, N_CTX / 128), 256>>>(
        Q, x, S, N_CTX, N_CTX, D_MODEL);

    // 3) P = causal_softmax(S), in place
    softmax_kernel<<<N_CTX, 256>>>(S, N_CTX);

    // 4) A = P @ x (k limited by causality)  [4096, 2048]
    gemm_kernel<0, 0, 1><<<dim3(D_MODEL / 128, N_CTX / 128), 256>>>(
        S, x, A, N_CTX, D_MODEL, N_CTX);

    // 5) out = A @ Wov^T                     [4096, 2048]
    gemm_kernel<1, 0, 0><<<dim3(D_MODEL / 128, N_CTX / 128), 256>>>(
        A, Wov, out, N_CTX, D_MODEL, D_MODEL);
}

// round 2
// speedup vs baseline: 1.8071x; 1.8071x over previous
#include <cuda_runtime.h>
#include <math.h>
#include <stdint.h>

#define N_CTX   4096
#define D_MODEL 2048

// Scratch (allocation-free rule: __device__ globals)
__device__ float g_Q[(size_t)N_CTX * D_MODEL];   // 32 MB
__device__ float g_S[(size_t)N_CTX * N_CTX];     // 64 MB
__device__ float g_A[(size_t)N_CTX * D_MODEL];   // 32 MB

// ---------------------------------------------------------------------------
// helpers
// ---------------------------------------------------------------------------
__device__ __forceinline__ uint32_t f2tf32(float x) {
    uint32_t r;
    asm("cvt.rna.tf32.f32 %0, %1;" : "=r"(r) : "f"(x));
    return r;
}

__device__ __forceinline__ void mma_tf32(float c[4],
                                         uint32_t a0, uint32_t a1, uint32_t a2, uint32_t a3,
                                         uint32_t b0, uint32_t b1) {
    asm volatile(
        "mma.sync.aligned.m16n8k8.row.col.f32.tf32.tf32.f32 "
        "{%0,%1,%2,%3}, {%4,%5,%6,%7}, {%8,%9}, {%0,%1,%2,%3};"
        : "+f"(c[0]), "+f"(c[1]), "+f"(c[2]), "+f"(c[3])
        : "r"(a0), "r"(a1), "r"(a2), "r"(a3), "r"(b0), "r"(b1));
}

__device__ __forceinline__ void cp_async16(void* smem, const void* gmem) {
    uint32_t s = (uint32_t)__cvta_generic_to_shared(smem);
    asm volatile("cp.async.cg.shared.global [%0], [%1], 16;" :: "r"(s), "l"(gmem));
}
__device__ __forceinline__ void cp_async4(void* smem, const void* gmem) {
    uint32_t s = (uint32_t)__cvta_generic_to_shared(smem);
    asm volatile("cp.async.ca.shared.global [%0], [%1], 4;" :: "r"(s), "l"(gmem));
}

// ---------------------------------------------------------------------------
// tf32 tensor-core GEMM:  C[M,N] = A[M,K] @ op(B)
//   TRANS_B=1: B is [N,K] row-major (C = A @ B^T);  TRANS_B=0: B is [K,N]
//   CAUSAL_SKIP: skip blocks fully above the diagonal (scores GEMM)
//   CAUSAL_K:    limit k-loop to k < m0+BM (P @ x GEMM)
//   SPLIT3:      3xTF32 error compensation (fp32-class accuracy)
// Block 128x128x16, 8 warps (2x4), warp tile 64x32, m16n8k8 fragments.
// ---------------------------------------------------------------------------
template <int TRANS_B, int CAUSAL_SKIP, int CAUSAL_K, int SPLIT3>
__global__ __launch_bounds__(256, 1)
void mma_gemm(const float* __restrict__ A,
              const float* __restrict__ B,
              float* __restrict__ C,
              int M, int N, int K)
{
    constexpr int BM = 128, BN = 128, BK = 16, LDP = 20; // LDP: padded row stride
    __shared__ float As[2][BM][LDP];
    __shared__ float Bs[2][BN][LDP];

    const int m0 = blockIdx.y * BM;
    const int n0 = blockIdx.x * BN;
    if (CAUSAL_SKIP && n0 >= m0 + BM) return;

    const int kEnd = CAUSAL_K ? min(K, m0 + BM) : K;
    const int nK   = kEnd / BK;

    const int tid  = threadIdx.x;
    const int warp = tid >> 5;
    const int lane = tid & 31;
    const int wm0  = (warp & 1) * 64;   // warp m-origin within block
    const int wn0  = (warp >> 1) * 32;  // warp n-origin within block
    const int g    = lane >> 2;         // groupID
    const int tg   = lane & 3;          // thread-in-group

    float acc[4][4][4];
    #pragma unroll
    for (int i = 0; i < 4; i++)
        #pragma unroll
        for (int j = 0; j < 4; j++)
            #pragma unroll
            for (int r = 0; r < 4; r++)
                acc[i][j][r] = 0.0f;

    auto loadStage = [&](int buf, int k0) {
        // A tile: [BM x BK] row-major slices, 16B cp.async
        #pragma unroll
        for (int i = 0; i < 2; i++) {
            int idx = tid + i * 256;
            int row = idx >> 2;
            int c4  = (idx & 3) * 4;
            cp_async16(&As[buf][row][c4], A + (size_t)(m0 + row) * K + k0 + c4);
        }
        if (TRANS_B) {
            #pragma unroll
            for (int i = 0; i < 2; i++) {
                int idx = tid + i * 256;
                int row = idx >> 2;
                int c4  = (idx & 3) * 4;
                cp_async16(&Bs[buf][row][c4], B + (size_t)(n0 + row) * K + k0 + c4);
            }
        } else {
            // B[K][N] -> Bs[n][k], 4B cp.async, coalesced along n
            #pragma unroll
            for (int i = 0; i < 8; i++) {
                int e = tid + i * 256;
                int k = e >> 7;
                int n = e & 127;
                cp_async4(&Bs[buf][n][k], B + (size_t)(k0 + k) * N + n0 + n);
            }
        }
    };

    auto compute = [&](int buf) {
        #pragma unroll
        for (int ks = 0; ks < 2; ks++) {
            const int kb = ks * 8;
            uint32_t Ab[4][4], Asm[4][4];
            uint32_t Bb[4][2], Bsm[4][2];

            #pragma unroll
            for (int mt = 0; mt < 4; mt++) {
                float v0 = As[buf][wm0 + mt * 16 + g    ][kb + tg    ];
                float v1 = As[buf][wm0 + mt * 16 + g + 8][kb + tg    ];
                float v2 = As[buf][wm0 + mt * 16 + g    ][kb + tg + 4];
                float v3 = As[buf][wm0 + mt * 16 + g + 8][kb + tg + 4];
                Ab[mt][0] = f2tf32(v0); Ab[mt][1] = f2tf32(v1);
                Ab[mt][2] = f2tf32(v2); Ab[mt][3] = f2tf32(v3);
                if (SPLIT3) {
                    Asm[mt][0] = f2tf32(v0 - __uint_as_float(Ab[mt][0]));
                    Asm[mt][1] = f2tf32(v1 - __uint_as_float(Ab[mt][1]));
                    Asm[mt][2] = f2tf32(v2 - __uint_as_float(Ab[mt][2]));
                    Asm[mt][3] = f2tf32(v3 - __uint_as_float(Ab[mt][3]));
                }
            }
            #pragma unroll
            for (int nt = 0; nt < 4; nt++) {
                float w0 = Bs[buf][wn0 + nt * 8 + g][kb + tg    ];
                float w1 = Bs[buf][wn0 + nt * 8 + g][kb + tg + 4];
                Bb[nt][0] = f2tf32(w0); Bb[nt][1] = f2tf32(w1);
                if (SPLIT3) {
                    Bsm[nt][0] = f2tf32(w0 - __uint_as_float(Bb[nt][0]));
                    Bsm[nt][1] = f2tf32(w1 - __uint_as_float(Bb[nt][1]));
                }
            }
            #pragma unroll
            for (int mt = 0; mt < 4; mt++) {
                #pragma unroll
                for (int nt = 0; nt < 4; nt++) {
                    if (SPLIT3) {
                        // small terms first, big last (better summation order)
                        mma_tf32(acc[mt][nt], Asm[mt][0], Asm[mt][1], Asm[mt][2], Asm[mt][3],
                                 Bb[nt][0], Bb[nt][1]);
                        mma_tf32(acc[mt][nt], Ab[mt][0], Ab[mt][1], Ab[mt][2], Ab[mt][3],
                                 Bsm[nt][0], Bsm[nt][1]);
                    }
                    mma_tf32(acc[mt][nt], Ab[mt][0], Ab[mt][1], Ab[mt][2], Ab[mt][3],
                             Bb[nt][0], Bb[nt][1]);
                }
            }
        }
    };

    loadStage(0, 0);
    asm volatile("cp.async.commit_group;" ::: "memory");

    for (int kt = 0; kt < nK; kt++) {
        if (kt + 1 < nK) {
            loadStage((kt + 1) & 1, (kt + 1) * BK);
            asm volatile("cp.async.commit_group;" ::: "memory");
            asm volatile("cp.async.wait_group 1;" ::: "memory");
        } else {
            asm volatile("cp.async.wait_group 0;" ::: "memory");
        }
        __syncthreads();
        compute(kt & 1);
        __syncthreads();
    }

    // store: each mma tile -> float2 per (row-half)
    #pragma unroll
    for (int mt = 0; mt < 4; mt++) {
        #pragma unroll
        for (int nt = 0; nt < 4; nt++) {
            int r = m0 + wm0 + mt * 16 + g;
            int c = n0 + wn0 + nt * 8 + 2 * tg;
            *(float2*)(C + (size_t)r * N + c)       = make_float2(acc[mt][nt][0], acc[mt][nt][1]);
            *(float2*)(C + (size_t)(r + 8) * N + c) = make_float2(acc[mt][nt][2], acc[mt][nt][3]);
        }
    }
}

// ---------------------------------------------------------------------------
// Causal row softmax, in place. One block per row.
// ---------------------------------------------------------------------------
__global__ __launch_bounds__(256)
void softmax_kernel(float* __restrict__ S, int n)
{
    const int row   = blockIdx.x;
    float* srow     = S + (size_t)row * n;
    const int valid = row + 1;
    const int tid   = threadIdx.x;

    __shared__ float red[256];

    float m = -INFINITY;
    for (int j = tid; j < valid; j += 256) m = fmaxf(m, srow[j]);
    red[tid] = m;
    __syncthreads();
    #pragma unroll
    for (int s = 128; s > 0; s >>= 1) {
        if (tid < s) red[tid] = fmaxf(red[tid], red[tid + s]);
        __syncthreads();
    }
    m = red[0];
    __syncthreads();

    float sum = 0.0f;
    for (int j = tid; j < valid; j += 256) sum += __expf(srow[j] - m);
    red[tid] = sum;
    __syncthreads();
    #pragma unroll
    for (int s = 128; s > 0; s >>= 1) {
        if (tid < s) red[tid] += red[tid + s];
        __syncthreads();
    }
    sum = red[0];
    const float inv = 1.0f / sum;

    for (int j = tid; j < n; j += 256) {
        float v = (j < valid) ? __expf(srow[j] - m) * inv : 0.0f;
        srow[j] = v;
    }
}

// ---------------------------------------------------------------------------
extern "C" void kernel_launch(void* const* d_in, const int* in_sizes, int n_in,
                              void* d_out, int out_size)
{
    const float* x   = (const float*)d_in[0];
    const float* Wqk = (const float*)d_in[1];
    const float* Wov = (const float*)d_in[2];
    float* out       = (float*)d_out;

    float *Q, *S, *A;
    cudaGetSymbolAddress((void**)&Q, g_Q);
    cudaGetSymbolAddress((void**)&S, g_S);
    cudaGetSymbolAddress((void**)&A, g_A);

    // 1) Q = x @ Wqk^T   (3xTF32: feeds scores, precision-critical)
    mma_gemm<1, 0, 0, 1><<<dim3(D_MODEL / 128, N_CTX / 128), 256>>>(
        x, Wqk, Q, N_CTX, D_MODEL, D_MODEL);

    // 2) S = Q @ x^T  (causal blocks only, 3xTF32)
    mma_gemm<1, 1, 0, 1><<<dim3(N_CTX / 128, N_CTX / 128), 256>>>(
        Q, x, S, N_CTX, N_CTX, D_MODEL);

    // 3) P = causal_softmax(S), in place
    softmax_kernel<<<N_CTX, 256>>>(S, N_CTX);

    // 4) A = P @ x  (k limited by causality, plain tf32)
    mma_gemm<0, 0, 1, 0><<<dim3(D_MODEL / 128, N_CTX / 128), 256>>>(
        S, x, A, N_CTX, D_MODEL, N_CTX);

    // 5) out = A @ Wov^T  (plain tf32)
    mma_gemm<1, 0, 0, 0><<<dim3(D_MODEL / 128, N_CTX / 128), 256>>>(
        A, Wov, out, N_CTX, D_MODEL, D_MODEL);
}